// round 17
// baseline (speedup 1.0000x reference)
#include <cuda_runtime.h>
#include <cuda_bf16.h>
#include <cstdint>

#define NPROMPT 50
#define MPAD 64              // padded prompt count (GEMM M)
#define D 768
#define KC 64                // k per chunk
#define NCHUNK (D / KC)      // 12
#define NTILE 128            // pe rows per CTA (GEMM N)
#define NVEC 201728          // 1024 * 197
#define NBLK (NVEC / NTILE)  // 1576
#define EPSV 1e-6f
#define NTHREADS 512

#define LDA 72               // A smem row stride (halves), 144B
#define LDBF 72              // B fp32 smem row stride (floats), 288B (==8 words mod 32)

__device__ __align__(16) __nv_bfloat16 g_B[MPAD * D];
__device__ float g_ns[MPAD];
__device__ double g_acc;

// ---------------------------------------------------------------- prep ----
__global__ void prep_kernel(const float* __restrict__ src) {
    int p = blockIdx.x, tid = threadIdx.x;
    float local = 0.f;
    for (int k = tid; k < D; k += blockDim.x) {
        float v = (p < NPROMPT) ? src[p * D + k] + EPSV : 0.f;
        g_B[p * D + k] = __float2bfloat16(v);
        local += v * v;
    }
    __shared__ float sh[256];
    sh[tid] = local;
    __syncthreads();
    for (int s = 128; s > 0; s >>= 1) {
        if (tid < s) sh[tid] += sh[tid + s];
        __syncthreads();
    }
    if (tid == 0) {
        g_ns[p] = sh[0];
        if (p == 0) g_acc = 0.0;
    }
}

// ------------------------------------------------------------- helpers ----
__device__ __forceinline__ void ldsm4(uint32_t& r0, uint32_t& r1, uint32_t& r2,
                                      uint32_t& r3, uint32_t addr) {
    asm volatile("ldmatrix.sync.aligned.m8n8.x4.shared.b16 {%0,%1,%2,%3}, [%4];\n"
                 : "=r"(r0), "=r"(r1), "=r"(r2), "=r"(r3)
                 : "r"(addr));
}

__device__ __forceinline__ void mma16816(float* c, uint32_t a0, uint32_t a1,
                                         uint32_t a2, uint32_t a3, uint32_t b0,
                                         uint32_t b1) {
    asm volatile(
        "mma.sync.aligned.m16n8k16.row.col.f32.bf16.bf16.f32 "
        "{%0,%1,%2,%3}, {%4,%5,%6,%7}, {%8,%9}, {%0,%1,%2,%3};\n"
        : "+f"(c[0]), "+f"(c[1]), "+f"(c[2]), "+f"(c[3])
        : "r"(a0), "r"(a1), "r"(a2), "r"(a3), "r"(b0), "r"(b1));
}

__device__ __forceinline__ void cp_async16(uint32_t dst, const void* src) {
    asm volatile("cp.async.cg.shared.global [%0], [%1], 16;" ::"r"(dst),
                 "l"(src)
                 : "memory");
}
#define CP_COMMIT() asm volatile("cp.async.commit_group;" ::: "memory")
#define CP_WAIT0() asm volatile("cp.async.wait_group 0;" ::: "memory")

__device__ __forceinline__ float2 lds64f(uint32_t a) {
    float2 r;
    asm volatile("ld.shared.v2.f32 {%0,%1}, [%2];"
                 : "=f"(r.x), "=f"(r.y)
                 : "r"(a));
    return r;
}
__device__ __forceinline__ float4 lds128f(uint32_t a) {
    float4 r;
    asm volatile("ld.shared.v4.f32 {%0,%1,%2,%3}, [%4];"
                 : "=f"(r.x), "=f"(r.y), "=f"(r.z), "=f"(r.w)
                 : "r"(a));
    return r;
}
// pack (lo=f.x, hi=f.y) as bf16x2 — PTX cvt packs operand a into hi, b into lo
__device__ __forceinline__ uint32_t cvtbf2(float2 f) {
    uint32_t r;
    asm volatile("cvt.rn.bf16x2.f32 %0, %1, %2;" : "=r"(r) : "f"(f.y), "f"(f.x));
    return r;
}

// ---------------------------------------------------------------- main ----
// smem: A db [2 x 64 x 144B] = 18432, B fp32 db [2 x 128 x 288B] = 73728,
//       norms: sNpe[128], sNs[64], sRed[16]  -> ~93KB, 2 CTAs/SM
constexpr int SA_STAGE = MPAD * LDA * 2;       // 9216 B
constexpr int SBF_STAGE = NTILE * LDBF * 4;    // 36864 B
constexpr int OFF_SA = 0;
constexpr int OFF_SBF = 2 * SA_STAGE;          // 18432
constexpr int OFF_NORM = OFF_SBF + 2 * SBF_STAGE;  // 92160
constexpr int SMEM_BYTES = OFF_NORM + (NTILE + MPAD + 16) * 4;

__global__ void __launch_bounds__(NTHREADS, 2)
dist_kernel(const float* __restrict__ pe) {
    extern __shared__ char smem_raw[];
    float* sNpe = (float*)(smem_raw + OFF_NORM);
    float* sNs = sNpe + NTILE;
    float* sRed = sNs + MPAD;

    const int tid = threadIdx.x;
    const int warp = tid >> 5, lane = tid & 31;
    const int m_base = (warp >> 2) * 16;  // 4 m-groups over M=64
    const int n_base = (warp & 3) * 32;   // 4 n-groups over N=128

    if (tid < MPAD) sNs[tid] = g_ns[tid];

    const uint32_t smem_u = (uint32_t)__cvta_generic_to_shared(smem_raw);
    const uint32_t sA_u = smem_u + OFF_SA;
    const uint32_t sBf_u = smem_u + OFF_SBF;

    // ---- B cp.async mapping: 4 threads/row, coalesced slots (tid&3)+4j
    const float* peBase = pe + (size_t)blockIdx.x * NTILE * D;
    const int r0 = tid >> 2;           // 0..127 (pe row)
    const int q4 = tid & 3;            // 16B slot base
    const float* bSrc = peBase + (size_t)r0 * D + q4 * 4;
    const uint32_t bDst = sBf_u + (uint32_t)(r0 * (LDBF * 4) + q4 * 16);

    // ---- A cp.async: 8 threads/row, 1 x 16B slot each
    const int ra = tid >> 3;
    const int qa = tid & 7;
    const uint32_t aDst = sA_u + (uint32_t)(ra * LDA + qa * 8) * 2;
    const __nv_bfloat16* aSrc = g_B + ra * D + qa * 8;

#define CPB(ck, buf)                                                          \
    {                                                                         \
        uint32_t d = bDst + (uint32_t)((buf)*SBF_STAGE);                      \
        const float* s = bSrc + (ck)*KC;                                      \
        cp_async16(d, s);                                                     \
        cp_async16(d + 64, s + 16);                                           \
        cp_async16(d + 128, s + 32);                                          \
        cp_async16(d + 192, s + 48);                                          \
    }
#define CPA(ck, buf)                                                          \
    cp_async16(aDst + (uint32_t)((buf)*SA_STAGE), aSrc + (ck)*KC)

    // accumulators: warp tile M16 x N32 -> 4 n8 tiles at n_base + jj*8
    float acc[4][4];
#pragma unroll
    for (int j = 0; j < 4; ++j)
#pragma unroll
        for (int q = 0; q < 4; ++q) acc[j][q] = 0.f;

    // A ldsm geometry (unchanged from validated kernel)
    const uint32_t a_off =
        (uint32_t)((m_base + (lane & 15)) * LDA + (lane >> 4) * 8) * 2;
    // B fragment geometry: n = n_base + jj*8 + lane/4, k = (lane&3)*2 (+8 for b1)
    const uint32_t bfr_off =
        (uint32_t)((n_base + (lane >> 2)) * (LDBF * 4) + (lane & 3) * 8);
    const int er = lane >> 2, ec2 = (lane & 3) * 2;

    float nacc = 0.f;

#define STEP(s, abase, bfbase)                                                \
    {                                                                         \
        uint32_t a0, a1, a2, a3;                                              \
        ldsm4(a0, a1, a2, a3, (abase) + a_off + (s)*32);                      \
        _Pragma("unroll") for (int jj = 0; jj < 4; ++jj) {                    \
            uint32_t ba =                                                     \
                (bfbase) + bfr_off + (uint32_t)(jj * 8 * LDBF * 4) + (s)*64;  \
            float2 f0 = lds64f(ba);                                           \
            float2 f1 = lds64f(ba + 32);                                      \
            mma16816(acc[jj], a0, a1, a2, a3, cvtbf2(f0), cvtbf2(f1));        \
        }                                                                     \
    }
#define STEPS4(buf)                                                           \
    {                                                                         \
        const uint32_t ab_ = sA_u + (uint32_t)((buf)*SA_STAGE);               \
        const uint32_t bb_ = sBf_u + (uint32_t)((buf)*SBF_STAGE);             \
        STEP(0, ab_, bb_);                                                    \
        STEP(1, ab_, bb_);                                                    \
        STEP(2, ab_, bb_);                                                    \
        STEP(3, ab_, bb_);                                                    \
    }
#define NACC(buf)                                                             \
    {                                                                         \
        uint32_t nb_ = sBf_u + (uint32_t)((buf)*SBF_STAGE) +                  \
                       (uint32_t)(r0 * (LDBF * 4) + q4 * 64);                 \
        _Pragma("unroll") for (int j = 0; j < 4; ++j) {                       \
            float4 f = lds128f(nb_ + j * 16);                                 \
            nacc += f.x * f.x + f.y * f.y + f.z * f.z + f.w * f.w;            \
        }                                                                     \
    }

    // prologue: chunk 0 -> buffer 0
    CPB(0, 0);
    CPA(0, 0);
    CP_COMMIT();
    CP_WAIT0();
    __syncthreads();

#pragma unroll 1
    for (int it = 0; it < NCHUNK; ++it) {
        const int cur = it & 1, nb = (it + 1) & 1;
        const bool dl = (it + 1) < NCHUNK;
        if (dl) { CPB(it + 1, nb); CPA(it + 1, nb); CP_COMMIT(); }
        STEPS4(cur);
        NACC(cur);
        if (dl) CP_WAIT0();
        __syncthreads();
    }

    // ---- |pe|^2 per row: combine the four quarter-row partials
    nacc += __shfl_xor_sync(0xffffffffu, nacc, 1);
    nacc += __shfl_xor_sync(0xffffffffu, nacc, 2);
    if ((tid & 3) == 0) sNpe[r0] = nacc;
    __syncthreads();

    // ---- epilogue: d = sqrt(|s'|^2 + |pe|^2 - 2 dot), mask prompts >= 50
    float lsum = 0.f;
#pragma unroll
    for (int j = 0; j < 4; ++j) {
        int n = n_base + j * 8 + ec2;
        float np0 = sNpe[n], np1 = sNpe[n + 1];
        int m0 = m_base + er;
        if (m0 < NPROMPT) {
            float ns0 = sNs[m0];
            lsum += sqrtf(fmaxf(ns0 + np0 - 2.f * acc[j][0], 0.f));
            lsum += sqrtf(fmaxf(ns0 + np1 - 2.f * acc[j][1], 0.f));
        }
        int m1 = m0 + 8;
        if (m1 < NPROMPT) {
            float ns1 = sNs[m1];
            lsum += sqrtf(fmaxf(ns1 + np0 - 2.f * acc[j][2], 0.f));
            lsum += sqrtf(fmaxf(ns1 + np1 - 2.f * acc[j][3], 0.f));
        }
    }
#pragma unroll
    for (int o = 16; o > 0; o >>= 1)
        lsum += __shfl_xor_sync(0xffffffffu, lsum, o);
    if (lane == 0) sRed[warp] = lsum;
    __syncthreads();
    if (warp == 0) {
        float sv = (lane < 16) ? sRed[lane] : 0.f;
#pragma unroll
        for (int o = 8; o > 0; o >>= 1)
            sv += __shfl_xor_sync(0xffffffffu, sv, o);
        if (lane == 0) atomicAdd(&g_acc, (double)sv);
    }
}

// -------------------------------------------------------------- finish ----
__global__ void finish_kernel(float* out) {
    out[0] = (float)(g_acc * (1.0 / ((double)NPROMPT * 197.0 * 1024.0)));
}

// -------------------------------------------------------------- launch ----
extern "C" void kernel_launch(void* const* d_in, const int* in_sizes, int n_in,
                              void* d_out, int out_size) {
    const float* src = (const float*)d_in[0];  // source_prompt [50,768]
    const float* pe = (const float*)d_in[1];   // patch_embeds [1024,197,768]
    float* out = (float*)d_out;

    cudaFuncSetAttribute(dist_kernel, cudaFuncAttributeMaxDynamicSharedMemorySize,
                         SMEM_BYTES);

    prep_kernel<<<MPAD, 256>>>(src);
    dist_kernel<<<NBLK, NTHREADS, SMEM_BYTES>>>(pe);
    finish_kernel<<<1, 1>>>(out);
}